// round 7
// baseline (speedup 1.0000x reference)
#include <cuda_runtime.h>

#define FULL 0xFFFFFFFFu

// Problem constants
#define BATCH 32
#define IN    2048
#define OUT   2048
#define KNUM  8
#define HDIM  512
#define KSZ   (IN * OUT)          // 4M elements per expert

#define IBLK   512                // i-range per main block (4 x 128 halves)
#define NCHUNK (IN / IBLK)        // 4
#define OBLK   16                 // o's per block (8 warps x 2 o)
#define NOBLK  (OUT / OBLK)       // 128
#define XSTR   516                // x_s row stride: lane byte-step 16 -> conflict-free LDS.128

// Scratch (device globals; fully overwritten every call -> graph-replay safe)
__device__ float g_h_partial[64 * HDIM];
__device__ float g_alpha[KNUM];

// ---------------------------------------------------------------------------
// K0a: partials of h = cond @ w1 (64 blocks x 512 thr, 32 rows each)
// ---------------------------------------------------------------------------
__global__ void mlp1_kernel(const float* __restrict__ cond,
                            const float* __restrict__ w1) {
    int j  = threadIdx.x;         // 0..511
    int p  = blockIdx.x;          // 0..63
    int i0 = p * 32;
    float s0 = 0.f, s1 = 0.f, s2 = 0.f, s3 = 0.f;
#pragma unroll
    for (int i = 0; i < 32; i += 4) {
        s0 += cond[i0 + i]     * w1[(i0 + i) * HDIM + j];
        s1 += cond[i0 + i + 1] * w1[(i0 + i + 1) * HDIM + j];
        s2 += cond[i0 + i + 2] * w1[(i0 + i + 2) * HDIM + j];
        s3 += cond[i0 + i + 3] * w1[(i0 + i + 3) * HDIM + j];
    }
    g_h_partial[p * HDIM + j] = (s0 + s1) + (s2 + s3);
}

// ---------------------------------------------------------------------------
// K0b: reduce 64 partials (float4, 4-way p-split), relu, scores, softmax
// ---------------------------------------------------------------------------
__global__ void mlp2_kernel(const float* __restrict__ b1,
                            const float* __restrict__ w2,
                            const float* __restrict__ b2) {
    __shared__ float4 hq_s[4][HDIM / 4];
    __shared__ float  h_s[HDIM];
    __shared__ float  s_s[KNUM];
    int t  = threadIdx.x;         // 512 threads
    int q  = t >> 7;              // p-quarter 0..3 (16 partials each)
    int j4 = t & 127;             // float4 index over HDIM

    const float4* hp4 = reinterpret_cast<const float4*>(g_h_partial);
    float4 s = make_float4(0.f, 0.f, 0.f, 0.f);
#pragma unroll
    for (int p = 0; p < 16; ++p) {
        float4 v = hp4[(q * 16 + p) * (HDIM / 4) + j4];
        s.x += v.x; s.y += v.y; s.z += v.z; s.w += v.w;
    }
    hq_s[q][j4] = s;
    __syncthreads();

    if (t < HDIM / 4) {
        float4 v0 = hq_s[0][t], v1 = hq_s[1][t],
               v2 = hq_s[2][t], v3 = hq_s[3][t];
        const float4* b14 = reinterpret_cast<const float4*>(b1);
        float4 bb = b14[t];
        h_s[t * 4 + 0] = fmaxf((v0.x + v1.x) + (v2.x + v3.x) + bb.x, 0.f);
        h_s[t * 4 + 1] = fmaxf((v0.y + v1.y) + (v2.y + v3.y) + bb.y, 0.f);
        h_s[t * 4 + 2] = fmaxf((v0.z + v1.z) + (v2.z + v3.z) + bb.z, 0.f);
        h_s[t * 4 + 3] = fmaxf((v0.w + v1.w) + (v2.w + v3.w) + bb.w, 0.f);
    }
    __syncthreads();

    int wid = t >> 5, lane = t & 31;
    if (wid < KNUM) {
        float sc = 0.f;
#pragma unroll
        for (int m = 0; m < HDIM / 32; ++m) {
            int jj = lane + m * 32;
            sc += h_s[jj] * w2[jj * KNUM + wid];
        }
#pragma unroll
        for (int off = 16; off; off >>= 1) sc += __shfl_xor_sync(FULL, sc, off);
        if (lane == 0) s_s[wid] = sc + b2[wid];
    }
    __syncthreads();
    if (t == 0) {
        float mx = -1e30f;
#pragma unroll
        for (int k = 0; k < KNUM; ++k) mx = fmaxf(mx, s_s[k]);
        float e[KNUM];
        float sum = 0.f;
#pragma unroll
        for (int k = 0; k < KNUM; ++k) { e[k] = __expf(s_s[k] - mx); sum += e[k]; }
        float inv = 1.f / sum;
#pragma unroll
        for (int k = 0; k < KNUM; ++k) g_alpha[k] = e[k] * inv;
    }
}

// ---------------------------------------------------------------------------
// K0c: zero `out` (also keeps main at global launch #4 for ncu)
// ---------------------------------------------------------------------------
__global__ void zero_out_kernel(float* __restrict__ out) {
    int idx = blockIdx.x * 256 + threadIdx.x;   // 0..16383 (float4 units)
    reinterpret_cast<float4*>(out)[idx] = make_float4(0.f, 0.f, 0.f, 0.f);
}

// ---------------------------------------------------------------------------
// Main: out[b,o] (+)= sum_{i in chunk} (sum_k a_k KW[k,o,i]) * x[b,i]
// grid = 512 blocks x 256 threads (8 warps x 2 o), 3 blocks/SM target.
// Per 128-i half: aggregate (curA k0-3 + curB k4-7) -> w4 -> STS;
//   reload curA(h+1) pre-compute, curB(h+1) mid-compute (staggered k-groups
//   keep hot registers ~85 so 3 blocks/SM fit). lane = batch row b.
// ---------------------------------------------------------------------------
__global__ __launch_bounds__(256, 3) void main_kernel(
        const float* __restrict__ x,    // [32, 2048]
        const float* __restrict__ kw,   // [8, 2048, 2048]
        const float* __restrict__ kb,   // [8, 2048]
        float* __restrict__ out) {      // [32, 2048]
    extern __shared__ float sm[];
    float* x_s   = sm;                            // 32 * 516 = 16512 floats
    float* w_s   = sm + BATCH * XSTR;             // 8 warps * 2 * 128 = 2048
    float* out_s = w_s;                           // aliased (used after sync)
    float* a_s   = w_s + 8 * 2 * 128;             // 8

    int t    = threadIdx.x;
    int wid  = t >> 5;
    int lane = t & 31;
    int ob   = blockIdx.x & (NOBLK - 1);          // 0..127
    int c    = blockIdx.x >> 7;                   // 0..3
    int i0   = c * IBLK;
    int o0   = ob * OBLK + wid;                   // warp's o pair: o0, o0+8

    if (t < KNUM) a_s[t] = g_alpha[t];

    const float* base0 = kw + (size_t)o0 * IN + i0 + lane * 4;
    const float* base1 = base0 + 8 * IN;          // o1 = o0 + 8

    // preload half 0 (both k-groups) BEFORE x staging (staging hides latency)
    float4 curA0[4], curA1[4], curB0[4], curB1[4];
#pragma unroll
    for (int k = 0; k < 4; ++k) {
        curA0[k] = *reinterpret_cast<const float4*>(base0 + (size_t)k * KSZ);
        curA1[k] = *reinterpret_cast<const float4*>(base1 + (size_t)k * KSZ);
    }
#pragma unroll
    for (int k = 0; k < 4; ++k) {
        curB0[k] = *reinterpret_cast<const float4*>(base0 + (size_t)(k + 4) * KSZ);
        curB1[k] = *reinterpret_cast<const float4*>(base1 + (size_t)(k + 4) * KSZ);
    }

    // stage x tile: x_s[b][il] = x[b][i0+il], float4
    const float4* x4 = reinterpret_cast<const float4*>(x);
#pragma unroll
    for (int jj = 0; jj < (BATCH * IBLK) / (4 * 256); ++jj) {
        int idx = jj * 256 + t;                   // 0..4095 float4 units
        int b   = idx >> 7;                       // 128 f4 per row
        int il4 = idx & 127;
        *reinterpret_cast<float4*>(&x_s[b * XSTR + il4 * 4]) =
            x4[(b * IN + i0) / 4 + il4];
    }
    __syncthreads();

    float4 acc0 = make_float4(0.f, 0.f, 0.f, 0.f);
    float4 acc1 = make_float4(0.f, 0.f, 0.f, 0.f);

#pragma unroll
    for (int h = 0; h < IBLK / 128; ++h) {
        // ---- aggregate experts (consumes curA, curB) ----
        float4 w40 = make_float4(0.f, 0.f, 0.f, 0.f);
        float4 w41 = make_float4(0.f, 0.f, 0.f, 0.f);
#pragma unroll
        for (int k = 0; k < 4; ++k) {
            float ak = a_s[k];
            w40.x += ak * curA0[k].x; w40.y += ak * curA0[k].y;
            w40.z += ak * curA0[k].z; w40.w += ak * curA0[k].w;
            w41.x += ak * curA1[k].x; w41.y += ak * curA1[k].y;
            w41.z += ak * curA1[k].z; w41.w += ak * curA1[k].w;
        }
#pragma unroll
        for (int k = 0; k < 4; ++k) {
            float ak = a_s[k + 4];
            w40.x += ak * curB0[k].x; w40.y += ak * curB0[k].y;
            w40.z += ak * curB0[k].z; w40.w += ak * curB0[k].w;
            w41.x += ak * curB1[k].x; w41.y += ak * curB1[k].y;
            w41.z += ak * curB1[k].z; w41.w += ak * curB1[k].w;
        }

        // ---- reload k-group A for next half (hidden under compute) ----
        if (h < IBLK / 128 - 1) {
            int off = (h + 1) * 128;
#pragma unroll
            for (int k = 0; k < 4; ++k) {
                curA0[k] = *reinterpret_cast<const float4*>(
                               base0 + (size_t)k * KSZ + off);
                curA1[k] = *reinterpret_cast<const float4*>(
                               base1 + (size_t)k * KSZ + off);
            }
        }

        // ---- stage aggregated strips (warp-private rows) ----
        *reinterpret_cast<float4*>(&w_s[(wid * 2 + 0) * 128 + lane * 4]) = w40;
        *reinterpret_cast<float4*>(&w_s[(wid * 2 + 1) * 128 + lane * 4]) = w41;
        __syncwarp();

        // ---- compute first 16 iters ----
#pragma unroll 8
        for (int src = 0; src < 16; ++src) {
            float4 xq  = *reinterpret_cast<const float4*>(
                             &x_s[lane * XSTR + h * 128 + src * 4]);
            float4 wq0 = *reinterpret_cast<const float4*>(
                             &w_s[(wid * 2 + 0) * 128 + src * 4]);
            float4 wq1 = *reinterpret_cast<const float4*>(
                             &w_s[(wid * 2 + 1) * 128 + src * 4]);
            acc0.x += wq0.x * xq.x; acc0.y += wq0.y * xq.y;
            acc0.z += wq0.z * xq.z; acc0.w += wq0.w * xq.w;
            acc1.x += wq1.x * xq.x; acc1.y += wq1.y * xq.y;
            acc1.z += wq1.z * xq.z; acc1.w += wq1.w * xq.w;
        }

        // ---- reload k-group B for next half ----
        if (h < IBLK / 128 - 1) {
            int off = (h + 1) * 128;
#pragma unroll
            for (int k = 0; k < 4; ++k) {
                curB0[k] = *reinterpret_cast<const float4*>(
                               base0 + (size_t)(k + 4) * KSZ + off);
                curB1[k] = *reinterpret_cast<const float4*>(
                               base1 + (size_t)(k + 4) * KSZ + off);
            }
        }

        // ---- compute last 16 iters ----
#pragma unroll 8
        for (int src = 16; src < 32; ++src) {
            float4 xq  = *reinterpret_cast<const float4*>(
                             &x_s[lane * XSTR + h * 128 + src * 4]);
            float4 wq0 = *reinterpret_cast<const float4*>(
                             &w_s[(wid * 2 + 0) * 128 + src * 4]);
            float4 wq1 = *reinterpret_cast<const float4*>(
                             &w_s[(wid * 2 + 1) * 128 + src * 4]);
            acc0.x += wq0.x * xq.x; acc0.y += wq0.y * xq.y;
            acc0.z += wq0.z * xq.z; acc0.w += wq0.w * xq.w;
            acc1.x += wq1.x * xq.x; acc1.y += wq1.y * xq.y;
            acc1.z += wq1.z * xq.z; acc1.w += wq1.w * xq.w;
        }
        __syncwarp();   // before w_s overwrite next half
    }

    // ---- epilogue: bias (c==0 only), transpose via w_s alias, atomic add ----
    float bb0 = 0.f, bb1 = 0.f;
    if (c == 0) {
#pragma unroll
        for (int k = 0; k < KNUM; ++k) {
            bb0 += a_s[k] * kb[k * OUT + o0];
            bb1 += a_s[k] * kb[k * OUT + o0 + 8];
        }
    }
    float v0 = (acc0.x + acc0.y) + (acc0.z + acc0.w) + bb0;
    float v1 = (acc1.x + acc1.y) + (acc1.z + acc1.w) + bb1;

    __syncthreads();                 // all warps done reading w_s
    out_s[lane * 17 + wid]     = v0; // lane = b
    out_s[lane * 17 + wid + 8] = v1;
    __syncthreads();
#pragma unroll
    for (int r = 0; r < 2; ++r) {
        int idx = r * 256 + t;                    // 0..511
        int b   = idx >> 4;
        int oi  = idx & 15;
        atomicAdd(&out[b * OUT + ob * OBLK + oi], out_s[b * 17 + oi]);
    }
}

// ---------------------------------------------------------------------------
extern "C" void kernel_launch(void* const* d_in, const int* in_sizes, int n_in,
                              void* d_out, int out_size) {
    const float* x    = (const float*)d_in[0];
    const float* cond = (const float*)d_in[1];
    const float* w1   = (const float*)d_in[2];
    const float* b1   = (const float*)d_in[3];
    const float* w2   = (const float*)d_in[4];
    const float* b2   = (const float*)d_in[5];
    const float* kw   = (const float*)d_in[6];
    const float* kb   = (const float*)d_in[7];
    float* out = (float*)d_out;

    const int SMEM_MAIN = (BATCH * XSTR + 8 * 2 * 128 + 8) * 4;  // 74.3 KB
    static int smem_set = 0;
    if (!smem_set) {
        cudaFuncSetAttribute(main_kernel,
                             cudaFuncAttributeMaxDynamicSharedMemorySize,
                             SMEM_MAIN);
        smem_set = 1;
    }

    mlp1_kernel<<<64, HDIM>>>(cond, w1);
    mlp2_kernel<<<1, HDIM>>>(b1, w2, b2);
    zero_out_kernel<<<(BATCH * OUT) / (4 * 256), 256>>>(out);
    main_kernel<<<NCHUNK * NOBLK, 256, SMEM_MAIN>>>(x, kw, kb, out);
}

// round 8
// speedup vs baseline: 1.3623x; 1.3623x over previous
#include <cuda_runtime.h>

#define FULL 0xFFFFFFFFu

// Problem constants
#define BATCH 32
#define IN    2048
#define OUT   2048
#define KNUM  8
#define HDIM  512
#define KSZ   (IN * OUT)          // 4M elements per expert

#define IBLK   512                // i-range per main block (4 x 128 halves)
#define NCHUNK (IN / IBLK)        // 4
#define OBLK   16                 // o's per block (8 warps x 2 o)
#define NOBLK  (OUT / OBLK)       // 128
#define XSTR   516                // x_s row stride (516%32==4 -> conflict-free LDS.128)

// Scratch (device globals; fully overwritten every call -> graph-replay safe)
__device__ float g_h_partial[128 * HDIM];
__device__ float g_alpha[KNUM];

// ---------------------------------------------------------------------------
// K0a: partials of h = cond @ w1 (128 blocks x 512 thr, 16 rows each,
//      8 independent accumulators -> 2 latency rounds instead of 8)
// ---------------------------------------------------------------------------
__global__ void mlp1_kernel(const float* __restrict__ cond,
                            const float* __restrict__ w1) {
    int j  = threadIdx.x;         // 0..511
    int p  = blockIdx.x;          // 0..127
    int i0 = p * 16;
    float s[8];
#pragma unroll
    for (int u = 0; u < 8; ++u)
        s[u] = cond[i0 + u] * w1[(i0 + u) * HDIM + j];
#pragma unroll
    for (int u = 0; u < 8; ++u)
        s[u] += cond[i0 + 8 + u] * w1[(i0 + 8 + u) * HDIM + j];
    g_h_partial[p * HDIM + j] =
        ((s[0] + s[1]) + (s[2] + s[3])) + ((s[4] + s[5]) + (s[6] + s[7]));
}

// ---------------------------------------------------------------------------
// K0b: reduce 128 partials (float4, 4-way p-split), relu, scores, softmax
// ---------------------------------------------------------------------------
__global__ void mlp2_kernel(const float* __restrict__ b1,
                            const float* __restrict__ w2,
                            const float* __restrict__ b2) {
    __shared__ float4 hq_s[4][HDIM / 4];
    __shared__ float  h_s[HDIM];
    __shared__ float  s_s[KNUM];
    int t  = threadIdx.x;         // 512 threads
    int q  = t >> 7;              // p-quarter 0..3 (32 partials each)
    int j4 = t & 127;             // float4 index over HDIM

    const float4* hp4 = reinterpret_cast<const float4*>(g_h_partial);
    float4 s = make_float4(0.f, 0.f, 0.f, 0.f);
#pragma unroll
    for (int p = 0; p < 32; ++p) {
        float4 v = hp4[(q * 32 + p) * (HDIM / 4) + j4];
        s.x += v.x; s.y += v.y; s.z += v.z; s.w += v.w;
    }
    hq_s[q][j4] = s;
    __syncthreads();

    if (t < HDIM / 4) {
        float4 v0 = hq_s[0][t], v1 = hq_s[1][t],
               v2 = hq_s[2][t], v3 = hq_s[3][t];
        const float4* b14 = reinterpret_cast<const float4*>(b1);
        float4 bb = b14[t];
        h_s[t * 4 + 0] = fmaxf((v0.x + v1.x) + (v2.x + v3.x) + bb.x, 0.f);
        h_s[t * 4 + 1] = fmaxf((v0.y + v1.y) + (v2.y + v3.y) + bb.y, 0.f);
        h_s[t * 4 + 2] = fmaxf((v0.z + v1.z) + (v2.z + v3.z) + bb.z, 0.f);
        h_s[t * 4 + 3] = fmaxf((v0.w + v1.w) + (v2.w + v3.w) + bb.w, 0.f);
    }
    __syncthreads();

    int wid = t >> 5, lane = t & 31;
    if (wid < KNUM) {
        float sc = 0.f;
#pragma unroll
        for (int m = 0; m < HDIM / 32; ++m) {
            int jj = lane + m * 32;
            sc += h_s[jj] * w2[jj * KNUM + wid];
        }
#pragma unroll
        for (int off = 16; off; off >>= 1) sc += __shfl_xor_sync(FULL, sc, off);
        if (lane == 0) s_s[wid] = sc + b2[wid];
    }
    __syncthreads();
    if (t == 0) {
        float mx = -1e30f;
#pragma unroll
        for (int k = 0; k < KNUM; ++k) mx = fmaxf(mx, s_s[k]);
        float e[KNUM];
        float sum = 0.f;
#pragma unroll
        for (int k = 0; k < KNUM; ++k) { e[k] = __expf(s_s[k] - mx); sum += e[k]; }
        float inv = 1.f / sum;
#pragma unroll
        for (int k = 0; k < KNUM; ++k) g_alpha[k] = e[k] * inv;
    }
}

// ---------------------------------------------------------------------------
// K0c: zero `out` (also keeps main at global launch #4 for ncu)
// ---------------------------------------------------------------------------
__global__ void zero_out_kernel(float* __restrict__ out) {
    int idx = blockIdx.x * 256 + threadIdx.x;   // 0..16383 (float4 units)
    reinterpret_cast<float4*>(out)[idx] = make_float4(0.f, 0.f, 0.f, 0.f);
}

// ---------------------------------------------------------------------------
// Main: out[b,o] (+)= sum_{i in chunk} (sum_k a_k KW[k,o,i]) * x[b,i]
// grid = 512 blocks x 256 threads (8 warps x 2 o), 2 blocks/SM, no spills.
// DESYNC: warp wid walks the 4 halves in rotated order h=(hh+wid)&3 so the
// SM's warps are never all in the same (load vs compute) phase -> DRAM stays
// busy through compute phases. lane = batch row b.
// ---------------------------------------------------------------------------
__global__ __launch_bounds__(256, 2) void main_kernel(
        const float* __restrict__ x,    // [32, 2048]
        const float* __restrict__ kw,   // [8, 2048, 2048]
        const float* __restrict__ kb,   // [8, 2048]
        float* __restrict__ out) {      // [32, 2048]
    extern __shared__ float sm[];
    float* x_s   = sm;                            // 32 * 516 = 16512 floats
    float* w_s   = sm + BATCH * XSTR;             // 8 warps * 2 * 128 = 2048
    float* out_s = w_s;                           // aliased (used after sync)
    float* a_s   = w_s + 8 * 2 * 128;             // 8

    int t    = threadIdx.x;
    int wid  = t >> 5;
    int lane = t & 31;
    int ob   = blockIdx.x & (NOBLK - 1);          // 0..127
    int c    = blockIdx.x >> 7;                   // 0..3
    int i0   = c * IBLK;
    int o0   = ob * OBLK + wid;                   // warp's o pair: o0, o0+8

    if (t < KNUM) a_s[t] = g_alpha[t];

    const float* base0 = kw + (size_t)o0 * IN + i0 + lane * 4;
    const float* base1 = base0 + 8 * IN;          // o1 = o0 + 8

    // first half for this warp (rotated): issue loads BEFORE x staging
    int h_first = wid & 3;
    float4 cur0[KNUM], cur1[KNUM];
#pragma unroll
    for (int k = 0; k < KNUM; ++k) {
        cur0[k] = *reinterpret_cast<const float4*>(
                      base0 + (size_t)k * KSZ + h_first * 128);
        cur1[k] = *reinterpret_cast<const float4*>(
                      base1 + (size_t)k * KSZ + h_first * 128);
    }

    // stage x tile: x_s[b][il] = x[b][i0+il], float4 (full 512-i tile)
    const float4* x4 = reinterpret_cast<const float4*>(x);
#pragma unroll
    for (int jj = 0; jj < (BATCH * IBLK) / (4 * 256); ++jj) {
        int idx = jj * 256 + t;                   // 0..4095 float4 units
        int b   = idx >> 7;                       // 128 f4 per row
        int il4 = idx & 127;
        *reinterpret_cast<float4*>(&x_s[b * XSTR + il4 * 4]) =
            x4[(b * IN + i0) / 4 + il4];
    }
    __syncthreads();

    float a[KNUM];
#pragma unroll
    for (int k = 0; k < KNUM; ++k) a[k] = a_s[k];

    float4 acc0 = make_float4(0.f, 0.f, 0.f, 0.f);
    float4 acc1 = make_float4(0.f, 0.f, 0.f, 0.f);

#pragma unroll
    for (int hh = 0; hh < IBLK / 128; ++hh) {
        int h = (hh + wid) & 3;                   // rotated half order

        // ---- aggregate experts (consumes cur) ----
        float4 w40 = make_float4(0.f, 0.f, 0.f, 0.f);
        float4 w41 = make_float4(0.f, 0.f, 0.f, 0.f);
#pragma unroll
        for (int k = 0; k < KNUM; ++k) {
            float ak = a[k];
            w40.x += ak * cur0[k].x; w40.y += ak * cur0[k].y;
            w40.z += ak * cur0[k].z; w40.w += ak * cur0[k].w;
            w41.x += ak * cur1[k].x; w41.y += ak * cur1[k].y;
            w41.z += ak * cur1[k].z; w41.w += ak * cur1[k].w;
        }

        // ---- reload cur for next rotated half (hidden under compute) ----
        if (hh < IBLK / 128 - 1) {
            int hn = (hh + 1 + wid) & 3;
            int off = hn * 128;
#pragma unroll
            for (int k = 0; k < KNUM; ++k) {
                cur0[k] = *reinterpret_cast<const float4*>(
                              base0 + (size_t)k * KSZ + off);
                cur1[k] = *reinterpret_cast<const float4*>(
                              base1 + (size_t)k * KSZ + off);
            }
        }

        // ---- stage aggregated strips (warp-private rows) ----
        *reinterpret_cast<float4*>(&w_s[(wid * 2 + 0) * 128 + lane * 4]) = w40;
        *reinterpret_cast<float4*>(&w_s[(wid * 2 + 1) * 128 + lane * 4]) = w41;
        __syncwarp();

        // ---- compute: lane = b; 4 i per iter ----
#pragma unroll 8
        for (int src = 0; src < 32; ++src) {
            float4 xq  = *reinterpret_cast<const float4*>(
                             &x_s[lane * XSTR + h * 128 + src * 4]);
            float4 wq0 = *reinterpret_cast<const float4*>(
                             &w_s[(wid * 2 + 0) * 128 + src * 4]);
            float4 wq1 = *reinterpret_cast<const float4*>(
                             &w_s[(wid * 2 + 1) * 128 + src * 4]);
            acc0.x += wq0.x * xq.x; acc0.y += wq0.y * xq.y;
            acc0.z += wq0.z * xq.z; acc0.w += wq0.w * xq.w;
            acc1.x += wq1.x * xq.x; acc1.y += wq1.y * xq.y;
            acc1.z += wq1.z * xq.z; acc1.w += wq1.w * xq.w;
        }
        __syncwarp();   // before w_s overwrite next half
    }

    // ---- epilogue: bias (c==0 only), transpose via w_s alias, atomic add ----
    float bb0 = 0.f, bb1 = 0.f;
    if (c == 0) {
#pragma unroll
        for (int k = 0; k < KNUM; ++k) {
            bb0 += a[k] * kb[k * OUT + o0];
            bb1 += a[k] * kb[k * OUT + o0 + 8];
        }
    }
    float v0 = (acc0.x + acc0.y) + (acc0.z + acc0.w) + bb0;
    float v1 = (acc1.x + acc1.y) + (acc1.z + acc1.w) + bb1;

    __syncthreads();                 // all warps done reading w_s
    out_s[lane * 17 + wid]     = v0; // lane = b
    out_s[lane * 17 + wid + 8] = v1;
    __syncthreads();
#pragma unroll
    for (int r = 0; r < 2; ++r) {
        int idx = r * 256 + t;                    // 0..511
        int b   = idx >> 4;
        int oi  = idx & 15;
        atomicAdd(&out[b * OUT + ob * OBLK + oi], out_s[b * 17 + oi]);
    }
}

// ---------------------------------------------------------------------------
extern "C" void kernel_launch(void* const* d_in, const int* in_sizes, int n_in,
                              void* d_out, int out_size) {
    const float* x    = (const float*)d_in[0];
    const float* cond = (const float*)d_in[1];
    const float* w1   = (const float*)d_in[2];
    const float* b1   = (const float*)d_in[3];
    const float* w2   = (const float*)d_in[4];
    const float* b2   = (const float*)d_in[5];
    const float* kw   = (const float*)d_in[6];
    const float* kb   = (const float*)d_in[7];
    float* out = (float*)d_out;

    const int SMEM_MAIN = (BATCH * XSTR + 8 * 2 * 128 + 8) * 4;  // 74.3 KB
    static int smem_set = 0;
    if (!smem_set) {
        cudaFuncSetAttribute(main_kernel,
                             cudaFuncAttributeMaxDynamicSharedMemorySize,
                             SMEM_MAIN);
        smem_set = 1;
    }

    mlp1_kernel<<<128, HDIM>>>(cond, w1);
    mlp2_kernel<<<1, HDIM>>>(b1, w2, b2);
    zero_out_kernel<<<(BATCH * OUT) / (4 * 256), 256>>>(out);
    main_kernel<<<NCHUNK * NOBLK, 256, SMEM_MAIN>>>(x, kw, kb, out);
}